// round 14
// baseline (speedup 1.0000x reference)
#include <cuda_runtime.h>

#define FULL_MASK 0xFFFFFFFFu
static constexpr int HID = 32;
static constexpr int TT = 1024;

__device__ __forceinline__ unsigned long long pack2(float lo, float hi) {
    unsigned long long r;
    asm("mov.b64 %0, {%1, %2};" : "=l"(r) : "f"(lo), "f"(hi));
    return r;
}
__device__ __forceinline__ void unpack2(unsigned long long v, float& lo, float& hi) {
    asm("mov.b64 {%0, %1}, %2;" : "=f"(lo), "=f"(hi) : "l"(v));
}
__device__ __forceinline__ unsigned long long fma2(unsigned long long a,
                                                   unsigned long long b,
                                                   unsigned long long c) {
    unsigned long long d;
    asm("fma.rn.f32x2 %0, %1, %2, %3;" : "=l"(d) : "l"(a), "l"(b), "l"(c));
    return d;
}
__device__ __forceinline__ float tanh_approx(float x) {
    float r; asm("tanh.approx.f32 %0, %1;" : "=f"(r) : "f"(x)); return r;
}

// ONE cell per 64-thread CTA, K-dimension split across the 2 warps:
// warp w owns k = w*16 .. w*16+15 of all four gate rows -> 64 weight regs
// (vs 128), raising residency from 12 to 16 warps/SM (4/SMSP).
// Both warps hold redundant full (h, c) state (lane j owns hidden unit j);
// each publishes h to its OWN buffer (per-warp in-order STS->LDS, validated
// R11), computes its half dot products (32 fma2, four 8-deep chains),
// exchanges 4 scalar partials per lane as one float4 (ping-ponged), one
// 2-warp __syncthreads, then both warps redundantly do activations + c,h.
// Exactness across the pair: final gate = mine + partner (commutative IEEE
// add -> bitwise identical in both warps; base carried by warp0 only).
__global__ void __launch_bounds__(64, 8)
lstm_kernel(const float* __restrict__ x,
            const float* __restrict__ W_ih,
            const float* __restrict__ W_hh,
            const float* __restrict__ b_ih,
            const float* __restrict__ b_hh,
            const float* __restrict__ fc_W,
            const float* __restrict__ fc_b,
            float* __restrict__ out, int B)
{
    __shared__ __align__(16) float  hb[2][2][HID];   // [warp][pp][hid]
    __shared__ __align__(16) float4 pb[2][2][HID];   // [warp][pp][lane] partials

    const int tid  = threadIdx.x;
    const int wid  = tid >> 5;            // 0 or 1: k-half owner
    const int lane = tid & 31;            // hidden unit owned by this lane
    const int b    = blockIdx.x;
    const int k0   = wid * 16;            // my k-half base

    // Gate order (PyTorch): rows [0:32)=i, [32:64)=f, [64:96)=g, [96:128)=o
    // Prescale i,f,o by 0.5 (sigmoid via 0.5+0.5*tanh(x/2)); g unscaled.
    const float gscale[4] = { 0.5f, 0.5f, 1.0f, 0.5f };
    unsigned long long Wg[4][8];          // 4 gates x 8 k-pairs of MY half
    #pragma unroll
    for (int g = 0; g < 4; ++g) {
        const float* wrow = W_hh + (g * HID + lane) * HID + k0;
        const float sc = gscale[g];
        #pragma unroll
        for (int kp = 0; kp < 8; ++kp)
            Wg[g][kp] = pack2(sc * wrow[2 * kp], sc * wrow[2 * kp + 1]);
    }
    // gate base: only warp0 carries it (so combined sum isn't doubled)
    const float wz = (wid == 0) ? 1.0f : 0.0f;
    const float wih_i = wz * 0.5f * W_ih[0 * HID + lane];
    const float wih_f = wz * 0.5f * W_ih[1 * HID + lane];
    const float wih_g = wz *        W_ih[2 * HID + lane];
    const float wih_o = wz * 0.5f * W_ih[3 * HID + lane];
    const float bias_i = wz * 0.5f * (b_ih[0 * HID + lane] + b_hh[0 * HID + lane]);
    const float bias_f = wz * 0.5f * (b_ih[1 * HID + lane] + b_hh[1 * HID + lane]);
    const float bias_g = wz *        (b_ih[2 * HID + lane] + b_hh[2 * HID + lane]);
    const float bias_o = wz * 0.5f * (b_ih[3 * HID + lane] + b_hh[3 * HID + lane]);

    float h = 0.0f, c = 0.0f;
    const float* xrow = x + (size_t)b * TT;   // x is [B, T, 1]
    float xbuf = xrow[lane];                  // both warps load identically

    for (int t0 = 0; t0 < TT; t0 += 32) {
        const int nidx = min(t0 + 32 + lane, TT - 1);
        const float xnext = xrow[nidx];       // prefetch (hidden)

        #pragma unroll 1
        for (int s = 0; s < 32; ++s) {
            // publish full h to MY buffer (in-order per-warp STS->LDS)
            float* hbu = hb[wid][s & 1];
            hbu[lane] = h;

            const float xv = __shfl_sync(FULL_MASK, xbuf, s);
            unsigned long long ai = pack2(fmaf(xv, wih_i, bias_i), 0.0f);
            unsigned long long af = pack2(fmaf(xv, wih_f, bias_f), 0.0f);
            unsigned long long ag = pack2(fmaf(xv, wih_g, bias_g), 0.0f);
            unsigned long long ao = pack2(fmaf(xv, wih_o, bias_o), 0.0f);

            // my k-half of h: 16 floats = 4 x LDS.128 broadcast
            const ulonglong2* hp =
                reinterpret_cast<const ulonglong2*>(hbu + k0);
            #pragma unroll
            for (int q = 0; q < 4; ++q) {
                const ulonglong2 hk = hp[q];
                ai = fma2(Wg[0][2 * q], hk.x, ai);
                af = fma2(Wg[1][2 * q], hk.x, af);
                ag = fma2(Wg[2][2 * q], hk.x, ag);
                ao = fma2(Wg[3][2 * q], hk.x, ao);
                ai = fma2(Wg[0][2 * q + 1], hk.y, ai);
                af = fma2(Wg[1][2 * q + 1], hk.y, af);
                ag = fma2(Wg[2][2 * q + 1], hk.y, ag);
                ao = fma2(Wg[3][2 * q + 1], hk.y, ao);
            }

            // horizontal add -> my 4 scalar partials; publish as one float4
            float lo, hi;
            unpack2(ai, lo, hi);  const float si = lo + hi;
            unpack2(af, lo, hi);  const float sf = lo + hi;
            unpack2(ag, lo, hi);  const float sg = lo + hi;
            unpack2(ao, lo, hi);  const float so = lo + hi;
            pb[wid][s & 1][lane] = make_float4(si, sf, sg, so);

            __syncthreads();   // 2-warp CTA barrier

            const float4 p = pb[wid ^ 1][s & 1][lane];
            // commutative add -> bitwise-identical gates in both warps
            const float ti = tanh_approx(si + p.x);
            const float tf = tanh_approx(sf + p.y);
            const float gg = tanh_approx(sg + p.z);
            const float to = tanh_approx(so + p.w);

            const float ig = fmaf(0.5f, ti, 0.5f);
            const float fg = fmaf(0.5f, tf, 0.5f);
            const float og = fmaf(0.5f, to, 0.5f);

            c = fmaf(fg, c, ig * gg);
            h = og * tanh_approx(c);
        }
        xbuf = xnext;
    }

    // out[b] = h . fc_W + fc_b  (warp0 reduces; warp1's h is identical)
    if (wid == 0) {
        float v = h * fc_W[lane];
        #pragma unroll
        for (int off = 16; off; off >>= 1)
            v += __shfl_xor_sync(FULL_MASK, v, off);
        if (lane == 0) out[b] = v + fc_b[0];
    }
}

extern "C" void kernel_launch(void* const* d_in, const int* in_sizes, int n_in,
                              void* d_out, int out_size) {
    const float* x    = (const float*)d_in[0];
    const float* W_ih = (const float*)d_in[1];
    const float* W_hh = (const float*)d_in[2];
    const float* b_ih = (const float*)d_in[3];
    const float* b_hh = (const float*)d_in[4];
    const float* fc_W = (const float*)d_in[5];
    const float* fc_b = (const float*)d_in[6];
    float* out = (float*)d_out;

    const int B = in_sizes[0] / TT;           // x is B*T*1 elements
    lstm_kernel<<<B, 64>>>(x, W_ih, W_hh, b_ih, b_hh, fc_W, fc_b, out, B);
}

// round 16
// speedup vs baseline: 1.7097x; 1.7097x over previous
#include <cuda_runtime.h>
#include <cstdint>

#define FULL_MASK 0xFFFFFFFFu
static constexpr int HID = 32;
static constexpr int TT  = 1024;
static constexpr int NC  = 32;        // cells per CTA
static constexpr int THREADS = 256;   // 8 warps: warp w owns gate rows 16w..16w+15

__device__ __forceinline__ float tanh_approx(float x) {
    float r; asm("tanh.approx.f32 %0, %1;" : "=f"(r) : "f"(x)); return r;
}
__device__ __forceinline__ uint32_t tf32u(float x) {
    uint32_t r; asm("cvt.rna.tf32.f32 %0, %1;" : "=r"(r) : "f"(x)); return r;
}
// m16n8k8 row.col f32.tf32.tf32.f32 (sm_80+; no 'a' target needed)
__device__ __forceinline__ void mma_tf32(float& c0, float& c1, float& c2, float& c3,
                                         uint32_t a0, uint32_t a1, uint32_t a2, uint32_t a3,
                                         uint32_t b0, uint32_t b1) {
    asm volatile(
        "mma.sync.aligned.m16n8k8.row.col.f32.tf32.tf32.f32 "
        "{%0,%1,%2,%3}, {%4,%5,%6,%7}, {%8,%9}, {%0,%1,%2,%3};"
        : "+f"(c0), "+f"(c1), "+f"(c2), "+f"(c3)
        : "r"(a0), "r"(a1), "r"(a2), "r"(a3), "r"(b0), "r"(b1));
}

// Fragment maps (PTX ISA, m16n8k8 tf32): gid=lane>>2, tg=lane&3
//  A: a0(gid,tg) a1(gid+8,tg) a2(gid,tg+4) a3(gid+8,tg+4)
//  B: b0(k=tg, n=gid) b1(k=tg+4, n=gid)
//  D: c0(gid,2tg) c1(gid,2tg+1) c2(gid+8,2tg) c3(gid+8,2tg+1)
//
// H smem layout engineered so a B-fragment load is exactly
//   b0 = H[kt*256 + nt*32 + lane], b1 = +128      (conflict-free LDS.32)
// via idx(k,n) = (k&3) + ((k>>2)&1)*128 + (k>>3)*256 + n*4.
// Epilogue h-write (k=4*sub+j, n=cell) lands at sub*128 + cell*4 + j -> STS.128.

__global__ void __launch_bounds__(THREADS, 1)
lstm_mma_kernel(const float* __restrict__ x, const float* __restrict__ W_ih,
                const float* __restrict__ W_hh, const float* __restrict__ b_ih,
                const float* __restrict__ b_hh, const float* __restrict__ fc_W,
                const float* __restrict__ fc_b, float* __restrict__ out, int B)
{
    __shared__ __align__(16) float Hsm[1024];       // H (tf32 bits), layout above
    __shared__ __align__(16) float Gsm[NC * 132];   // activated gates [cell][gaterow(+pad)]
    __shared__ __align__(16) float xsm[NC * 36];    // x chunk [cell][step], stride 36

    const int tid  = threadIdx.x;
    const int w    = tid >> 5;
    const int lane = tid & 31;
    const int gid  = lane >> 2, tg = lane & 3;
    const int gr   = 16 * w + gid;                  // my A row (and gr+8)
    const int gate = w >> 1;                        // 0=i 1=f 2=g 3=o
    const int cell = tid >> 3, sub = tid & 7, hq = sub * 4;
    const int cell0 = blockIdx.x * NC;

    // ---- preload A fragments: W_hh rows gr/gr+8, prescaled, tf32 ----
    const float sc = (gate == 2) ? 1.0f : 0.5f;     // sigmoid via 0.5+0.5*tanh(x/2)
    uint32_t a[4][4];
    #pragma unroll
    for (int kt = 0; kt < 4; ++kt) {
        const int k = kt * 8 + tg;
        a[kt][0] = tf32u(sc * W_hh[gr * HID + k]);
        a[kt][1] = tf32u(sc * W_hh[(gr + 8) * HID + k]);
        a[kt][2] = tf32u(sc * W_hh[gr * HID + k + 4]);
        a[kt][3] = tf32u(sc * W_hh[(gr + 8) * HID + k + 4]);
    }
    const float wA = sc * W_ih[gr];
    const float wB = sc * W_ih[gr + 8];
    const float bA = sc * (b_ih[gr] + b_hh[gr]);
    const float bB = sc * (b_ih[gr + 8] + b_hh[gr + 8]);

    // ---- init: H = 0 (h0), prime x prefetch regs with chunk 0 ----
    for (int i = tid; i < 1024; i += THREADS) Hsm[i] = 0.0f;
    // prefetch mapping: thread loads x[cell0+cc][ (tid&7)*4 + j ] (LDG.128)
    const int pc = tid >> 3, ps = (tid & 7) * 4;
    float4 xpre = *(const float4*)(x + (size_t)(cell0 + pc) * TT + ps);

    float c[4] = {0.f, 0.f, 0.f, 0.f};
    float h[4] = {0.f, 0.f, 0.f, 0.f};

    for (int t = 0; t < TT; ++t) {
        const int s = t & 31;
        if (s == 0) {
            __syncthreads();                        // xsm free; H(t) complete
            *(float4*)(xsm + pc * 36 + ps) = xpre;  // publish chunk
            __syncthreads();
            if (t + 32 < TT)                        // prefetch next (hidden 32 steps)
                xpre = *(const float4*)(x + (size_t)(cell0 + pc) * TT + t + 32 + ps);
        } else {
            __syncthreads();                        // sync1: H(t) written
        }

        // ---- acc init: exact fp32 x*W_ih + bias ----
        float acc[4][4];
        #pragma unroll
        for (int nt = 0; nt < 4; ++nt) {
            const int n0 = nt * 8 + 2 * tg;
            const float x0 = xsm[n0 * 36 + s];
            const float x1 = xsm[(n0 + 1) * 36 + s];
            acc[nt][0] = fmaf(x0, wA, bA);
            acc[nt][1] = fmaf(x1, wA, bA);
            acc[nt][2] = fmaf(x0, wB, bB);
            acc[nt][3] = fmaf(x1, wB, bB);
        }

        // ---- 16 mma: D += W_hh (tf32) * H (tf32) ----
        #pragma unroll
        for (int kt = 0; kt < 4; ++kt) {
            const int base = kt * 256 + lane;
            #pragma unroll
            for (int nt = 0; nt < 4; ++nt) {
                const uint32_t b0 = __float_as_uint(Hsm[base + nt * 32]);
                const uint32_t b1 = __float_as_uint(Hsm[base + nt * 32 + 128]);
                mma_tf32(acc[nt][0], acc[nt][1], acc[nt][2], acc[nt][3],
                         a[kt][0], a[kt][1], a[kt][2], a[kt][3], b0, b1);
            }
        }

        // ---- activate + exchange (Gsm[cell*132 + gaterow]) ----
        #pragma unroll
        for (int nt = 0; nt < 4; ++nt) {
            const int n0 = nt * 8 + 2 * tg;
            float v0 = tanh_approx(acc[nt][0]);
            float v1 = tanh_approx(acc[nt][1]);
            float v2 = tanh_approx(acc[nt][2]);
            float v3 = tanh_approx(acc[nt][3]);
            if (gate != 2) {
                v0 = fmaf(0.5f, v0, 0.5f);
                v1 = fmaf(0.5f, v1, 0.5f);
                v2 = fmaf(0.5f, v2, 0.5f);
                v3 = fmaf(0.5f, v3, 0.5f);
            }
            Gsm[n0 * 132 + gr]            = v0;
            Gsm[(n0 + 1) * 132 + gr]      = v1;
            Gsm[n0 * 132 + gr + 8]        = v2;
            Gsm[(n0 + 1) * 132 + gr + 8]  = v3;
        }
        __syncthreads();                            // sync2: gates ready

        // ---- epilogue: 1 thread = 4 hid of one cell ----
        const float4 gi = *(const float4*)(Gsm + cell * 132 +  0 + hq);
        const float4 gf = *(const float4*)(Gsm + cell * 132 + 32 + hq);
        const float4 gg = *(const float4*)(Gsm + cell * 132 + 64 + hq);
        const float4 go = *(const float4*)(Gsm + cell * 132 + 96 + hq);
        c[0] = fmaf(gf.x, c[0], gi.x * gg.x);
        c[1] = fmaf(gf.y, c[1], gi.y * gg.y);
        c[2] = fmaf(gf.z, c[2], gi.z * gg.z);
        c[3] = fmaf(gf.w, c[3], gi.w * gg.w);
        h[0] = go.x * tanh_approx(c[0]);
        h[1] = go.y * tanh_approx(c[1]);
        h[2] = go.z * tanh_approx(c[2]);
        h[3] = go.w * tanh_approx(c[3]);
        // write h (tf32 bits) for next step: contiguous STS.128
        *(float4*)(Hsm + sub * 128 + cell * 4) = make_float4(
            __uint_as_float(tf32u(h[0])), __uint_as_float(tf32u(h[1])),
            __uint_as_float(tf32u(h[2])), __uint_as_float(tf32u(h[3])));
    }

    // ---- out[cell] = h . fc_W + fc_b (reduce over 8 subs of a cell) ----
    float v = h[0] * fc_W[hq] + h[1] * fc_W[hq + 1] +
              h[2] * fc_W[hq + 2] + h[3] * fc_W[hq + 3];
    v += __shfl_down_sync(FULL_MASK, v, 4);
    v += __shfl_down_sync(FULL_MASK, v, 2);
    v += __shfl_down_sync(FULL_MASK, v, 1);
    if (sub == 0 && cell0 + cell < B)
        out[cell0 + cell] = v + fc_b[0];
}

extern "C" void kernel_launch(void* const* d_in, const int* in_sizes, int n_in,
                              void* d_out, int out_size) {
    const float* x    = (const float*)d_in[0];
    const float* W_ih = (const float*)d_in[1];
    const float* W_hh = (const float*)d_in[2];
    const float* b_ih = (const float*)d_in[3];
    const float* b_hh = (const float*)d_in[4];
    const float* fc_W = (const float*)d_in[5];
    const float* fc_b = (const float*)d_in[6];
    float* out = (float*)d_out;

    const int B = in_sizes[0] / TT;           // x is B*T*1 elements (B=4096)
    lstm_mma_kernel<<<B / NC, THREADS>>>(x, W_ih, W_hh, b_ih, b_hh,
                                         fc_W, fc_b, out, B);
}

// round 17
// speedup vs baseline: 2.2447x; 1.3129x over previous
#include <cuda_runtime.h>
#include <cstdint>

#define FULL_MASK 0xFFFFFFFFu
static constexpr int HID = 32;
static constexpr int TT  = 1024;
static constexpr int NC  = 8;         // cells per CTA
static constexpr int THREADS = 64;    // 2 warps: warp w owns gate rows 64w..64w+63

__device__ __forceinline__ float tanh_approx(float x) {
    float r; asm("tanh.approx.f32 %0, %1;" : "=f"(r) : "f"(x)); return r;
}
__device__ __forceinline__ uint32_t tf32u(float x) {
    uint32_t r; asm("cvt.rna.tf32.f32 %0, %1;" : "=r"(r) : "f"(x)); return r;
}
__device__ __forceinline__ void mma_tf32(float& c0, float& c1, float& c2, float& c3,
                                         uint32_t a0, uint32_t a1, uint32_t a2, uint32_t a3,
                                         uint32_t b0, uint32_t b1) {
    asm volatile(
        "mma.sync.aligned.m16n8k8.row.col.f32.tf32.tf32.f32 "
        "{%0,%1,%2,%3}, {%4,%5,%6,%7}, {%8,%9}, {%0,%1,%2,%3};"
        : "+f"(c0), "+f"(c1), "+f"(c2), "+f"(c3)
        : "r"(a0), "r"(a1), "r"(a2), "r"(a3), "r"(b0), "r"(b1));
}

// Fragment maps (validated in R16): gid=lane>>2, tg=lane&3
//  A: a0(gid,tg) a1(gid+8,tg) a2(gid,tg+4) a3(gid+8,tg+4)
//  B: b0(k=tg,n=gid) b1(k=tg+4,n=gid)
//  D: c0(gid,2tg) c1(gid,2tg+1) c2(gid+8,2tg) c3(gid+8,2tg+1)
// H layout (8 cells): idx(k,n) = (k&3) + ((k>>2)&1)*32 + (k>>3)*64 + n*4
//  -> b0 = Hsm[kt*64 + lane] (lane-linear, conflict-free), b1 = +32.
//  -> epilogue h-write (k=4sub+j, n=cell): float4 at (sub&1)*32+(sub>>1)*64+cell*4.

__global__ void __launch_bounds__(THREADS, 4)
lstm_mma_kernel(const float* __restrict__ x, const float* __restrict__ W_ih,
                const float* __restrict__ W_hh, const float* __restrict__ b_ih,
                const float* __restrict__ b_hh, const float* __restrict__ fc_W,
                const float* __restrict__ fc_b, float* __restrict__ out, int B)
{
    __shared__ __align__(16) float Hsm[256];        // H (tf32 bits), 8 cells x 32 k
    __shared__ __align__(16) float Gsm[NC * 132];   // activated gates [cell][gaterow+pad]
    __shared__ __align__(16) float xsm[NC * 36];    // x chunk [cell][step]

    const int tid  = threadIdx.x;
    const int w    = tid >> 5;                      // 0: gates i,f ; 1: g,o
    const int lane = tid & 31;
    const int gid  = lane >> 2, tg = lane & 3;
    const int cell = tid >> 3, sub = tid & 7, hq = sub * 4;
    const int cell0 = blockIdx.x * NC;

    // ---- preload A fragments: 4 m-tiles (rows 64w+16i+gid / +8), prescaled tf32 ----
    uint32_t a[4][4][4];                            // [mt][kt][reg]
    float wih[4][2], bias[4][2];
    #pragma unroll
    for (int i = 0; i < 4; ++i) {
        const int r0 = 64 * w + 16 * i + gid;       // + lane row gid
        const int gate = (64 * w + 16 * i) >> 5;    // 0=i 1=f 2=g 3=o
        const float sc = (gate == 2) ? 1.0f : 0.5f; // sigmoid via 0.5+0.5*tanh(x/2)
        #pragma unroll
        for (int kt = 0; kt < 4; ++kt) {
            const int k = kt * 8 + tg;
            a[i][kt][0] = tf32u(sc * W_hh[r0 * HID + k]);
            a[i][kt][1] = tf32u(sc * W_hh[(r0 + 8) * HID + k]);
            a[i][kt][2] = tf32u(sc * W_hh[r0 * HID + k + 4]);
            a[i][kt][3] = tf32u(sc * W_hh[(r0 + 8) * HID + k + 4]);
        }
        wih[i][0]  = sc * W_ih[r0];
        wih[i][1]  = sc * W_ih[r0 + 8];
        bias[i][0] = sc * (b_ih[r0] + b_hh[r0]);
        bias[i][1] = sc * (b_ih[r0 + 8] + b_hh[r0 + 8]);
    }

    // ---- init: H = 0 (h0); prime x prefetch (thread -> cell tid>>3, 4 steps) ----
    for (int i = tid; i < 256; i += THREADS) Hsm[i] = 0.0f;
    const int pc = tid >> 3, ps = (tid & 7) * 4;
    float4 xpre = *(const float4*)(x + (size_t)(cell0 + pc) * TT + ps);

    float c[4] = {0.f, 0.f, 0.f, 0.f};
    float h[4] = {0.f, 0.f, 0.f, 0.f};

    for (int t = 0; t < TT; ++t) {
        const int s = t & 31;
        if (s == 0) {
            __syncthreads();                        // xsm free; H(t) complete
            *(float4*)(xsm + pc * 36 + ps) = xpre;
            __syncthreads();
            if (t + 32 < TT)
                xpre = *(const float4*)(x + (size_t)(cell0 + pc) * TT + t + 32 + ps);
        } else {
            __syncthreads();                        // sync1: H(t) written
        }

        // ---- acc init: exact fp32 x*W_ih + bias (cols = cells 2tg, 2tg+1) ----
        const float x0 = xsm[(2 * tg) * 36 + s];
        const float x1 = xsm[(2 * tg + 1) * 36 + s];
        float acc[4][4];
        #pragma unroll
        for (int i = 0; i < 4; ++i) {
            acc[i][0] = fmaf(x0, wih[i][0], bias[i][0]);
            acc[i][1] = fmaf(x1, wih[i][0], bias[i][0]);
            acc[i][2] = fmaf(x0, wih[i][1], bias[i][1]);
            acc[i][3] = fmaf(x1, wih[i][1], bias[i][1]);
        }

        // ---- 16 mma: B-fragments shared across all 4 m-tiles ----
        #pragma unroll
        for (int kt = 0; kt < 4; ++kt) {
            const uint32_t b0 = __float_as_uint(Hsm[kt * 64 + lane]);
            const uint32_t b1 = __float_as_uint(Hsm[kt * 64 + lane + 32]);
            #pragma unroll
            for (int i = 0; i < 4; ++i)
                mma_tf32(acc[i][0], acc[i][1], acc[i][2], acc[i][3],
                         a[i][kt][0], a[i][kt][1], a[i][kt][2], a[i][kt][3],
                         b0, b1);
        }

        // ---- activate + exchange: Gsm[col*132 + row] ----
        #pragma unroll
        for (int i = 0; i < 4; ++i) {
            const int r0 = 64 * w + 16 * i + gid;
            const int gate = (64 * w + 16 * i) >> 5;
            float v0 = tanh_approx(acc[i][0]);
            float v1 = tanh_approx(acc[i][1]);
            float v2 = tanh_approx(acc[i][2]);
            float v3 = tanh_approx(acc[i][3]);
            if (gate != 2) {
                v0 = fmaf(0.5f, v0, 0.5f);
                v1 = fmaf(0.5f, v1, 0.5f);
                v2 = fmaf(0.5f, v2, 0.5f);
                v3 = fmaf(0.5f, v3, 0.5f);
            }
            Gsm[(2 * tg) * 132 + r0]         = v0;
            Gsm[(2 * tg + 1) * 132 + r0]     = v1;
            Gsm[(2 * tg) * 132 + r0 + 8]     = v2;
            Gsm[(2 * tg + 1) * 132 + r0 + 8] = v3;
        }
        __syncthreads();                            // sync2: gates ready

        // ---- epilogue: 1 thread = 4 hid of one cell ----
        const float4 gi = *(const float4*)(Gsm + cell * 132 +  0 + hq);
        const float4 gf = *(const float4*)(Gsm + cell * 132 + 32 + hq);
        const float4 gg = *(const float4*)(Gsm + cell * 132 + 64 + hq);
        const float4 go = *(const float4*)(Gsm + cell * 132 + 96 + hq);
        c[0] = fmaf(gf.x, c[0], gi.x * gg.x);
        c[1] = fmaf(gf.y, c[1], gi.y * gg.y);
        c[2] = fmaf(gf.z, c[2], gi.z * gg.z);
        c[3] = fmaf(gf.w, c[3], gi.w * gg.w);
        h[0] = go.x * tanh_approx(c[0]);
        h[1] = go.y * tanh_approx(c[1]);
        h[2] = go.z * tanh_approx(c[2]);
        h[3] = go.w * tanh_approx(c[3]);
        *(float4*)(Hsm + (sub & 1) * 32 + (sub >> 1) * 64 + cell * 4) = make_float4(
            __uint_as_float(tf32u(h[0])), __uint_as_float(tf32u(h[1])),
            __uint_as_float(tf32u(h[2])), __uint_as_float(tf32u(h[3])));
    }

    // ---- out[cell] = h . fc_W + fc_b (8 subs of a cell are contiguous lanes) ----
    float v = h[0] * fc_W[hq] + h[1] * fc_W[hq + 1] +
              h[2] * fc_W[hq + 2] + h[3] * fc_W[hq + 3];
    v += __shfl_down_sync(FULL_MASK, v, 4);
    v += __shfl_down_sync(FULL_MASK, v, 2);
    v += __shfl_down_sync(FULL_MASK, v, 1);
    if (sub == 0 && cell0 + cell < B)
        out[cell0 + cell] = v + fc_b[0];
}

extern "C" void kernel_launch(void* const* d_in, const int* in_sizes, int n_in,
                              void* d_out, int out_size) {
    const float* x    = (const float*)d_in[0];
    const float* W_ih = (const float*)d_in[1];
    const float* W_hh = (const float*)d_in[2];
    const float* b_ih = (const float*)d_in[3];
    const float* b_hh = (const float*)d_in[4];
    const float* fc_W = (const float*)d_in[5];
    const float* fc_b = (const float*)d_in[6];
    float* out = (float*)d_out;

    const int B = in_sizes[0] / TT;           // x is B*T*1 elements (B=4096)
    lstm_mma_kernel<<<B / NC, THREADS>>>(x, W_ih, W_hh, b_ih, b_hh,
                                         fc_W, fc_b, out, B);
}